// round 13
// baseline (speedup 1.0000x reference)
#include <cuda_runtime.h>
#include <cuda_fp16.h>
#include <cuda_bf16.h>
#include <mma.h>

using namespace nvcuda;

#define MQ 8
#define KQ 4096
#define DG 64
#define NB 32
#define HH 64
#define WW 64
#define H_ITER 16
#define RSTRIDE 36   // uints per smem row (144B): STS.128/LDS.128 aligned

// Scratch LUT in fp16: v[m,k,c]  (4 MB). uint4-typed for 16B alignment.
__device__ uint4 g_v4[MQ * KQ * (DG / 8)];

typedef unsigned long long ull;

// LUT load with L2 evict_last cache policy.
__device__ __forceinline__ uint4 ldg_el(const uint4* p, ull policy) {
    uint4 v;
    asm("ld.global.nc.L2::cache_hint.v4.u32 {%0,%1,%2,%3}, [%4], %5;"
        : "=r"(v.x), "=r"(v.y), "=r"(v.z), "=r"(v.w) : "l"(p), "l"(policy));
    return v;
}

__device__ __forceinline__ ull mk_evict_last_policy() {
    ull policy;
    asm("createpolicy.fractional.L2::evict_last.b64 %0, 1.0;" : "=l"(policy));
    return policy;
}

// ---------------------------------------------------------------------------
// Phase 1 (tensor cores): v[m, k, c] = sum_d codebook[m,k,d] * wv[m,c,d]
// wmma tf32 m16n16k8, fp32 accumulate. Block = 128 thr (4 warps), 64 k-rows.
// A = codebook[k][d] row-major (ld 64); B = wv[c][d] read col-major so that
// B(d, c) = wv[c][d] (ld 64). Result staged in smem fp32, written as fp16.
// ---------------------------------------------------------------------------
__global__ __launch_bounds__(128) void compute_v_kernel(
    const float* __restrict__ codebook,   // [M, K, DG]
    const float* __restrict__ wv)         // [M, DG(c), DG(d)]
{
    __shared__ float vsm[64 * 68];   // [k-row][c], pad 68

    const int m   = blockIdx.y;
    const int k0  = blockIdx.x * 64;
    const int tid = threadIdx.x;
    const int wid = tid >> 5;        // 0..3 -> k-rows wid*16..+16

    const float* cbm = codebook + ((long)m * KQ + k0 + wid * 16) * DG;
    const float* wvm = wv + m * 64 * 64;

    wmma::fragment<wmma::accumulator, 16, 16, 8, float> acc[4];
    #pragma unroll
    for (int j = 0; j < 4; j++) wmma::fill_fragment(acc[j], 0.0f);

    #pragma unroll
    for (int d0 = 0; d0 < 64; d0 += 8) {
        wmma::fragment<wmma::matrix_a, 16, 16, 8, wmma::precision::tf32,
                       wmma::row_major> a;
        wmma::load_matrix_sync(a, cbm + d0, 64);
        #pragma unroll
        for (int t = 0; t < a.num_elements; t++)
            a.x[t] = wmma::__float_to_tf32(a.x[t]);

        #pragma unroll
        for (int j = 0; j < 4; j++) {
            wmma::fragment<wmma::matrix_b, 16, 16, 8, wmma::precision::tf32,
                           wmma::col_major> b;
            wmma::load_matrix_sync(b, wvm + (j * 16) * 64 + d0, 64);
            #pragma unroll
            for (int t = 0; t < b.num_elements; t++)
                b.x[t] = wmma::__float_to_tf32(b.x[t]);
            wmma::mma_sync(acc[j], a, b, acc[j]);
        }
    }

    // Stage fp32 result in smem, then convert to fp16 and store coalesced.
    #pragma unroll
    for (int j = 0; j < 4; j++)
        wmma::store_matrix_sync(vsm + (wid * 16) * 68 + j * 16, acc[j], 68,
                                wmma::mem_row_major);
    __syncthreads();

    // 64 rows x 8 uint4 (fp16) = 512 uint4; 4 per thread.
    #pragma unroll
    for (int it = 0; it < 4; it++) {
        int idx = tid + it * 128;
        int row = idx >> 3, s = idx & 7;
        const float* src = vsm + row * 68 + s * 8;
        __half2 h[4];
        #pragma unroll
        for (int p = 0; p < 4; p++)
            h[p] = __floats2half2_rn(src[2 * p], src[2 * p + 1]);
        g_v4[(unsigned)(m * KQ + k0 + row) * 8u + (unsigned)s] =
            *reinterpret_cast<uint4*>(h);
    }
}

// ---------------------------------------------------------------------------
// Phase 2: pipelined gather (fp16 LUT, L2-evict_last policy) + transpose.
// R12-best: 256-thr block = (n, m, 16 h-rows), register prefetch,
// smem tile 64 rows x 36 uints, uint4-slot swizzle s ^= 2*(row&3).
// ---------------------------------------------------------------------------
__global__ __launch_bounds__(256) void gather_kernel(
    const int* __restrict__ codes,   // [N, H, W, M]
    float* __restrict__ out)         // [N, M*DG, H, W]
{
    __shared__ int  codes_s[H_ITER * 64];
    __shared__ uint4 vsq[64 * (RSTRIDE / 4) + 16];

    unsigned* vsu = reinterpret_cast<unsigned*>(vsq);

    const unsigned bid = blockIdx.x;     // [n(5) | m(3) | hg(2)]
    const unsigned hg = bid & 3;
    const unsigned m  = (bid >> 2) & 7;
    const unsigned n  = bid >> 5;
    const unsigned tid = threadIdx.x;
    const unsigned h0 = hg * H_ITER;

    const ull pol = mk_evict_last_policy();

    // Load codes for the whole h-group once.
    #pragma unroll
    for (int i = tid; i < H_ITER * 64; i += 256) {
        unsigned hh = (unsigned)i >> 6, w = (unsigned)i & 63;
        codes_s[i] = __ldg(&codes[((n * HH + h0 + hh) * WW + w) * MQ + m]);
    }
    __syncthreads();

    // Load mapping: q = uint4-slot (0..7); rows rw, rw+32.
    const unsigned q  = tid & 7;
    const unsigned rw = tid >> 3;            // 0..31
    const uint4* gv = g_v4;
    const unsigned mbase = m * (KQ * 8u);    // uint4 units

    // Store-phase mapping
    const unsigned w  = tid & 63;
    const unsigned cb = tid >> 6;            // 0..3 -> c in [cb*16, cb*16+16)
    float* outb = out + (unsigned)((n * 512u + m * 64u) * 4096u) + w;
    const unsigned wsw = 2u * (w & 3);
    const unsigned lbase = w * (RSTRIDE / 4);

    uint4 r0v, r1v;
    // Prefetch tile 0
    {
        unsigned c0 = (unsigned)codes_s[rw];
        unsigned c1 = (unsigned)codes_s[rw + 32];
        r0v = ldg_el(&gv[mbase + c0 * 8 + q], pol);
        r1v = ldg_el(&gv[mbase + c1 * 8 + q], pol);
    }

    const unsigned s0 = rw * RSTRIDE + 4 * (q ^ (2u * (rw & 3)));
    const unsigned s1 = (rw + 32) * RSTRIDE + 4 * (q ^ (2u * (rw & 3)));

    #pragma unroll 4
    for (int h = 0; h < H_ITER; h++) {
        // STS current tile: swizzled STS.128, conflict-free.
        *reinterpret_cast<uint4*>(vsu + s0) = r0v;
        *reinterpret_cast<uint4*>(vsu + s1) = r1v;
        __syncthreads();

        // Prefetch next tile — overlaps the store phase.
        if (h + 1 < H_ITER) {
            unsigned c0 = (unsigned)codes_s[(h + 1) * 64 + rw];
            unsigned c1 = (unsigned)codes_s[(h + 1) * 64 + rw + 32];
            r0v = ldg_el(&gv[mbase + c0 * 8 + q], pol);
            r1v = ldg_el(&gv[mbase + c1 * 8 + q], pol);
        }

        // Store phase: 2 swizzled LDS.128 -> cvt -> 16 coalesced STG.32.
        float* outp = outb + (h0 + (unsigned)h) * WW;
        #pragma unroll
        for (int sl = 0; sl < 2; sl++) {
            unsigned slot = (2u * cb + (unsigned)sl) ^ wsw;
            uint4 u = vsq[lbase + slot];
            unsigned c0 = cb * 16 + (unsigned)sl * 8;
            float2 f;
            f = __half22float2(*reinterpret_cast<__half2*>(&u.x));
            __stcs(&outp[(c0 + 0) * 4096u], f.x);
            __stcs(&outp[(c0 + 1) * 4096u], f.y);
            f = __half22float2(*reinterpret_cast<__half2*>(&u.y));
            __stcs(&outp[(c0 + 2) * 4096u], f.x);
            __stcs(&outp[(c0 + 3) * 4096u], f.y);
            f = __half22float2(*reinterpret_cast<__half2*>(&u.z));
            __stcs(&outp[(c0 + 4) * 4096u], f.x);
            __stcs(&outp[(c0 + 5) * 4096u], f.y);
            f = __half22float2(*reinterpret_cast<__half2*>(&u.w));
            __stcs(&outp[(c0 + 6) * 4096u], f.x);
            __stcs(&outp[(c0 + 7) * 4096u], f.y);
        }
        __syncthreads();
    }
}

extern "C" void kernel_launch(void* const* d_in, const int* in_sizes, int n_in,
                              void* d_out, int out_size)
{
    const int*   codes    = (const int*)d_in[0];    // (32,64,64,8) int32
    const float* codebook = (const float*)d_in[1];  // (8,4096,64) fp32
    const float* wv       = (const float*)d_in[2];  // (8,64,64) fp32
    float*       out      = (float*)d_out;          // (32,512,64,64) fp32

    (void)in_sizes; (void)n_in; (void)out_size;

    dim3 g1(KQ / 64, MQ);   // 512 blocks of 128 threads (4 warps)
    compute_v_kernel<<<g1, 128>>>(codebook, wv);

    // 32 * 8 * 4 = 1024 blocks, one per (n, m, 16-h group)
    gather_kernel<<<NB * MQ * (HH / H_ITER), 256>>>(codes, out);
}

// round 14
// speedup vs baseline: 1.1092x; 1.1092x over previous
#include <cuda_runtime.h>
#include <cuda_fp16.h>
#include <cuda_bf16.h>
#include <mma.h>

using namespace nvcuda;

#define MQ 8
#define KQ 4096
#define DG 64
#define NB 32
#define HH 64
#define WW 64
#define H_ITER 16
#define RSTRIDE 36   // uints per smem row (144B): STS.128/LDS.128 aligned

// Scratch LUT in fp16: v[m,k,c]  (4 MB). uint4-typed for 16B alignment.
__device__ uint4 g_v4[MQ * KQ * (DG / 8)];

typedef unsigned long long ull;

// LUT load with L2 evict_last cache policy.
__device__ __forceinline__ uint4 ldg_el(const uint4* p, ull policy) {
    uint4 v;
    asm("ld.global.nc.L2::cache_hint.v4.u32 {%0,%1,%2,%3}, [%4], %5;"
        : "=r"(v.x), "=r"(v.y), "=r"(v.z), "=r"(v.w) : "l"(p), "l"(policy));
    return v;
}

__device__ __forceinline__ ull mk_evict_last_policy() {
    ull policy;
    asm("createpolicy.fractional.L2::evict_last.b64 %0, 1.0;" : "=l"(policy));
    return policy;
}

// ---------------------------------------------------------------------------
// Phase 1 (tensor cores, smem-staged): v[m,k,c] = codebook[m,k,:].wv[m,c,:]
// Coalesced float4 gmem -> smem (stride 72), wmma tf32 from smem.
// Block = 128 thr (4 warps) handles 64 k-rows; warp w -> rows w*16..+16.
// Accumulators staged into the cb_s region (barrier-separated), fp16 out.
// ---------------------------------------------------------------------------
__global__ __launch_bounds__(128) void compute_v_kernel(
    const float* __restrict__ codebook,   // [M, K, DG]
    const float* __restrict__ wv)         // [M, DG(c), DG(d)]
{
    __shared__ float cb_s[64 * 72];   // [k][d]; later reused as vsm[64][68]
    __shared__ float wv_s[64 * 72];   // [c][d]

    const int m   = blockIdx.y;
    const int k0  = blockIdx.x * 64;
    const int tid = threadIdx.x;
    const int wid = tid >> 5;

    // Stage inputs: 1024 float4 each, coalesced.
    const float4* cb4 = reinterpret_cast<const float4*>(
        codebook + ((long)m * KQ + k0) * DG);
    const float4* wv4 = reinterpret_cast<const float4*>(wv + m * 64 * 64);
    #pragma unroll
    for (int it = 0; it < 8; it++) {
        int idx = tid + it * 128;
        int r = idx >> 4, d4 = idx & 15;
        *reinterpret_cast<float4*>(cb_s + r * 72 + d4 * 4) = cb4[idx];
        *reinterpret_cast<float4*>(wv_s + r * 72 + d4 * 4) = wv4[idx];
    }
    __syncthreads();

    wmma::fragment<wmma::accumulator, 16, 16, 8, float> acc[4];
    #pragma unroll
    for (int j = 0; j < 4; j++) wmma::fill_fragment(acc[j], 0.0f);

    #pragma unroll
    for (int d0 = 0; d0 < 64; d0 += 8) {
        wmma::fragment<wmma::matrix_a, 16, 16, 8, wmma::precision::tf32,
                       wmma::row_major> a;
        wmma::load_matrix_sync(a, cb_s + (wid * 16) * 72 + d0, 72);
        #pragma unroll
        for (int t = 0; t < a.num_elements; t++)
            a.x[t] = wmma::__float_to_tf32(a.x[t]);

        #pragma unroll
        for (int j = 0; j < 4; j++) {
            wmma::fragment<wmma::matrix_b, 16, 16, 8, wmma::precision::tf32,
                           wmma::col_major> b;
            wmma::load_matrix_sync(b, wv_s + (j * 16) * 72 + d0, 72);
            #pragma unroll
            for (int t = 0; t < b.num_elements; t++)
                b.x[t] = wmma::__float_to_tf32(b.x[t]);
            wmma::mma_sync(acc[j], a, b, acc[j]);
        }
    }
    __syncthreads();   // cb_s fully consumed; safe to reuse as vsm

    float* vsm = cb_s;   // [64][68]
    #pragma unroll
    for (int j = 0; j < 4; j++)
        wmma::store_matrix_sync(vsm + (wid * 16) * 68 + j * 16, acc[j], 68,
                                wmma::mem_row_major);
    __syncthreads();

    // 64 rows x 8 uint4 (fp16) = 512 uint4; 4 per thread, coalesced.
    #pragma unroll
    for (int it = 0; it < 4; it++) {
        int idx = tid + it * 128;
        int row = idx >> 3, s = idx & 7;
        const float* src = vsm + row * 68 + s * 8;
        __half2 h[4];
        #pragma unroll
        for (int p = 0; p < 4; p++)
            h[p] = __floats2half2_rn(src[2 * p], src[2 * p + 1]);
        g_v4[(unsigned)(m * KQ + k0 + row) * 8u + (unsigned)s] =
            *reinterpret_cast<uint4*>(h);
    }
}

// ---------------------------------------------------------------------------
// Phase 2: pipelined gather (fp16 LUT, L2-evict_last policy) + transpose.
// R12-best, unchanged: 256-thr block = (n, m, 16 h-rows), register prefetch,
// smem tile 64 rows x 36 uints, uint4-slot swizzle s ^= 2*(row&3).
// ---------------------------------------------------------------------------
__global__ __launch_bounds__(256) void gather_kernel(
    const int* __restrict__ codes,   // [N, H, W, M]
    float* __restrict__ out)         // [N, M*DG, H, W]
{
    __shared__ int  codes_s[H_ITER * 64];
    __shared__ uint4 vsq[64 * (RSTRIDE / 4) + 16];

    unsigned* vsu = reinterpret_cast<unsigned*>(vsq);

    const unsigned bid = blockIdx.x;     // [n(5) | m(3) | hg(2)]
    const unsigned hg = bid & 3;
    const unsigned m  = (bid >> 2) & 7;
    const unsigned n  = bid >> 5;
    const unsigned tid = threadIdx.x;
    const unsigned h0 = hg * H_ITER;

    const ull pol = mk_evict_last_policy();

    // Load codes for the whole h-group once.
    #pragma unroll
    for (int i = tid; i < H_ITER * 64; i += 256) {
        unsigned hh = (unsigned)i >> 6, w = (unsigned)i & 63;
        codes_s[i] = __ldg(&codes[((n * HH + h0 + hh) * WW + w) * MQ + m]);
    }
    __syncthreads();

    // Load mapping: q = uint4-slot (0..7); rows rw, rw+32.
    const unsigned q  = tid & 7;
    const unsigned rw = tid >> 3;            // 0..31
    const uint4* gv = g_v4;
    const unsigned mbase = m * (KQ * 8u);    // uint4 units

    // Store-phase mapping
    const unsigned w  = tid & 63;
    const unsigned cb = tid >> 6;            // 0..3 -> c in [cb*16, cb*16+16)
    float* outb = out + (unsigned)((n * 512u + m * 64u) * 4096u) + w;
    const unsigned wsw = 2u * (w & 3);
    const unsigned lbase = w * (RSTRIDE / 4);

    uint4 r0v, r1v;
    // Prefetch tile 0
    {
        unsigned c0 = (unsigned)codes_s[rw];
        unsigned c1 = (unsigned)codes_s[rw + 32];
        r0v = ldg_el(&gv[mbase + c0 * 8 + q], pol);
        r1v = ldg_el(&gv[mbase + c1 * 8 + q], pol);
    }

    const unsigned s0 = rw * RSTRIDE + 4 * (q ^ (2u * (rw & 3)));
    const unsigned s1 = (rw + 32) * RSTRIDE + 4 * (q ^ (2u * (rw & 3)));

    #pragma unroll 4
    for (int h = 0; h < H_ITER; h++) {
        // STS current tile: swizzled STS.128, conflict-free.
        *reinterpret_cast<uint4*>(vsu + s0) = r0v;
        *reinterpret_cast<uint4*>(vsu + s1) = r1v;
        __syncthreads();

        // Prefetch next tile — overlaps the store phase.
        if (h + 1 < H_ITER) {
            unsigned c0 = (unsigned)codes_s[(h + 1) * 64 + rw];
            unsigned c1 = (unsigned)codes_s[(h + 1) * 64 + rw + 32];
            r0v = ldg_el(&gv[mbase + c0 * 8 + q], pol);
            r1v = ldg_el(&gv[mbase + c1 * 8 + q], pol);
        }

        // Store phase: 2 swizzled LDS.128 -> cvt -> 16 coalesced STG.32.
        float* outp = outb + (h0 + (unsigned)h) * WW;
        #pragma unroll
        for (int sl = 0; sl < 2; sl++) {
            unsigned slot = (2u * cb + (unsigned)sl) ^ wsw;
            uint4 u = vsq[lbase + slot];
            unsigned c0 = cb * 16 + (unsigned)sl * 8;
            float2 f;
            f = __half22float2(*reinterpret_cast<__half2*>(&u.x));
            __stcs(&outp[(c0 + 0) * 4096u], f.x);
            __stcs(&outp[(c0 + 1) * 4096u], f.y);
            f = __half22float2(*reinterpret_cast<__half2*>(&u.y));
            __stcs(&outp[(c0 + 2) * 4096u], f.x);
            __stcs(&outp[(c0 + 3) * 4096u], f.y);
            f = __half22float2(*reinterpret_cast<__half2*>(&u.z));
            __stcs(&outp[(c0 + 4) * 4096u], f.x);
            __stcs(&outp[(c0 + 5) * 4096u], f.y);
            f = __half22float2(*reinterpret_cast<__half2*>(&u.w));
            __stcs(&outp[(c0 + 6) * 4096u], f.x);
            __stcs(&outp[(c0 + 7) * 4096u], f.y);
        }
        __syncthreads();
    }
}

extern "C" void kernel_launch(void* const* d_in, const int* in_sizes, int n_in,
                              void* d_out, int out_size)
{
    const int*   codes    = (const int*)d_in[0];    // (32,64,64,8) int32
    const float* codebook = (const float*)d_in[1];  // (8,4096,64) fp32
    const float* wv       = (const float*)d_in[2];  // (8,64,64) fp32
    float*       out      = (float*)d_out;          // (32,512,64,64) fp32

    (void)in_sizes; (void)n_in; (void)out_size;

    dim3 g1(KQ / 64, MQ);   // 512 blocks of 128 threads (4 warps)
    compute_v_kernel<<<g1, 128>>>(codebook, wv);

    // 32 * 8 * 4 = 1024 blocks, one per (n, m, 16-h group)
    gather_kernel<<<NB * MQ * (HH / H_ITER), 256>>>(codes, out);
}